// round 6
// baseline (speedup 1.0000x reference)
#include <cuda_runtime.h>
#include <cuda_bf16.h>
#include <math.h>

#define B 16
typedef unsigned long long ull;

// ---------------------------------------------------------------------------
// f32x2 packed helpers (Blackwell dual-fp32 pipe)
// ---------------------------------------------------------------------------
__device__ __forceinline__ void ffma2(ull &acc, ull a, ull b) {
    asm("fma.rn.f32x2 %0, %1, %2, %0;" : "+l"(acc) : "l"(a), "l"(b));
}
__device__ __forceinline__ ull pack2(float a, float b) {
    ull r; asm("mov.b64 %0, {%1, %2};" : "=l"(r) : "f"(a), "f"(b)); return r;
}
__device__ __forceinline__ float2 unpack2(ull v) {
    float2 r; asm("mov.b64 {%0, %1}, %2;" : "=f"(r.x), "=f"(r.y) : "l"(v)); return r;
}

// ---------------------------------------------------------------------------
// Scratch (device globals; no allocation allowed)
// ---------------------------------------------------------------------------
__device__ float g_h1[B*64*128*128];
__device__ float g_h2[B*128*64*64];
__device__ float g_feat[B*256*32*32];
__device__ float g_tok[B*1024*256];
__device__ float g_q[B*256*32*32];
__device__ float g_d1[B*128*64*64];
__device__ float g_d2[B*64*128*128];
__device__ int   g_idx[B*1024];
__device__ float g_pv[2*B*1024];
__device__ int   g_pi[2*B*1024];

// ---------------------------------------------------------------------------
// Direct conv k=4 s=2 p=1, 4 pixels/thread.  Tile 64x16, 8 oc.
// Per tap: 4 LDG + 4 pack + 4 LDS.64 + 16 FFMA2  -> fp-pipe bound.
// Requires Wout multiple of 64 is NOT required (guards), but best when so.
// ---------------------------------------------------------------------------
__global__ __launch_bounds__(256)
void conv_k4s2_p4(const float* __restrict__ x, const float* __restrict__ w,
                  const float* __restrict__ bias, float* __restrict__ y,
                  int N, int Cin, int Cout, int Hin, int Win, int relu)
{
    const int Hout = Hin >> 1, Wout = Win >> 1;
    const int ng = (Cout + 7) >> 3;
    const int n  = blockIdx.z / ng;
    const int oc0 = (blockIdx.z % ng) << 3;
    const int ox0 = blockIdx.x * 64 + threadIdx.x;
    const int oy  = blockIdx.y * 16 + threadIdx.y;
    const int tid = threadIdx.y * 16 + threadIdx.x;

    __shared__ float wsm[64][16][8];

    int iy[4]; bool oky[4];
    int ix[4][4]; bool okx[4][4];          // [kx][pixel]
#pragma unroll
    for (int k = 0; k < 4; k++) {
        int t = oy * 2 + k - 1;
        iy[k] = t; oky[k] = (unsigned)t < (unsigned)Hin;
#pragma unroll
        for (int p = 0; p < 4; p++) {
            int s = ox0 * 2 + k - 1 + 32 * p;    // +16 out pixels -> +32 in
            ix[k][p] = s;
            okx[k][p] = (unsigned)s < (unsigned)Win;
        }
    }

    ull acc[4][4];
#pragma unroll
    for (int p = 0; p < 4; p++)
#pragma unroll
        for (int j = 0; j < 4; j++) acc[p][j] = 0ull;

    for (int ic0 = 0; ic0 < Cin; ic0 += 64) {
        const int icc = min(64, Cin - ic0);
        __syncthreads();
        for (int i = tid; i < icc * 128; i += 256) {
            int c = i >> 7, rem = i & 127, t = rem >> 3, o = rem & 7;
            float wv = 0.f;
            if (oc0 + o < Cout)
                wv = w[(((oc0 + o) * Cin + ic0 + c) << 4) + t];
            wsm[c][t][o] = wv;
        }
        __syncthreads();

        const float* xp = x + ((size_t)(n * Cin + ic0) * Hin) * Win;
        for (int c = 0; c < icc; c++) {
            const float* xc = xp + (size_t)c * Hin * Win;
#pragma unroll
            for (int ky = 0; ky < 4; ky++) {
                if (!oky[ky]) continue;
                const float* xr = xc + iy[ky] * Win;
#pragma unroll
                for (int kx = 0; kx < 4; kx++) {
                    ull vd[4];
#pragma unroll
                    for (int p = 0; p < 4; p++) {
                        float v = okx[kx][p] ? __ldg(&xr[ix[kx][p]]) : 0.f;
                        vd[p] = pack2(v, v);
                    }
                    const ull* wp = (const ull*)&wsm[c][ky * 4 + kx][0];
#pragma unroll
                    for (int j = 0; j < 4; j++) {
                        ull wj = wp[j];
#pragma unroll
                        for (int p = 0; p < 4; p++)
                            ffma2(acc[p][j], vd[p], wj);
                    }
                }
            }
        }
    }

#pragma unroll
    for (int p = 0; p < 4; p++) {
        int ox = ox0 + 16 * p;
        if (ox >= Wout) continue;
#pragma unroll
        for (int j = 0; j < 4; j++) {
            float2 r = unpack2(acc[p][j]);
            int oc = oc0 + 2 * j;
            if (oc < Cout) {
                float v = r.x + bias[oc];
                if (relu) v = fmaxf(v, 0.f);
                y[(((size_t)n * Cout + oc) * Hout + oy) * Wout + ox] = v;
            }
            if (oc + 1 < Cout) {
                float v = r.y + bias[oc + 1];
                if (relu) v = fmaxf(v, 0.f);
                y[(((size_t)n * Cout + oc + 1) * Hout + oy) * Wout + ox] = v;
            }
        }
    }
}

// ---------------------------------------------------------------------------
// R4 2-pixel conv (verified) — used for conv3 (Wout=32).
// ---------------------------------------------------------------------------
__global__ __launch_bounds__(256)
void conv_k4s2(const float* __restrict__ x, const float* __restrict__ w,
               const float* __restrict__ bias, float* __restrict__ y,
               int N, int Cin, int Cout, int Hin, int Win, int relu)
{
    const int Hout = Hin >> 1, Wout = Win >> 1;
    const int ng = (Cout + 7) >> 3;
    const int n  = blockIdx.z / ng;
    const int oc0 = (blockIdx.z % ng) << 3;
    const int ox0 = blockIdx.x * 32 + threadIdx.x;
    const int oy  = blockIdx.y * 16 + threadIdx.y;
    const int tid = threadIdx.y * 16 + threadIdx.x;

    __shared__ float wsm[64][16][8];

    int iy[4]; bool oky[4];
    int ixA[4], ixB[4]; bool okA[4], okB[4];
#pragma unroll
    for (int k = 0; k < 4; k++) {
        int t = oy * 2 + k - 1;
        iy[k] = t; oky[k] = (unsigned)t < (unsigned)Hin;
        int sA = ox0 * 2 + k - 1;
        ixA[k] = sA; okA[k] = (unsigned)sA < (unsigned)Win;
        int sB = sA + 32;
        ixB[k] = sB; okB[k] = (unsigned)sB < (unsigned)Win;
    }

    ull acc[2][4];
#pragma unroll
    for (int p = 0; p < 2; p++)
#pragma unroll
        for (int j = 0; j < 4; j++) acc[p][j] = 0ull;

    for (int ic0 = 0; ic0 < Cin; ic0 += 64) {
        const int icc = min(64, Cin - ic0);
        __syncthreads();
        for (int i = tid; i < icc * 128; i += 256) {
            int c = i >> 7, rem = i & 127, t = rem >> 3, o = rem & 7;
            float wv = 0.f;
            if (oc0 + o < Cout)
                wv = w[(((oc0 + o) * Cin + ic0 + c) << 4) + t];
            wsm[c][t][o] = wv;
        }
        __syncthreads();

        const float* xp = x + ((size_t)(n * Cin + ic0) * Hin) * Win;
        for (int c = 0; c < icc; c++) {
            const float* xc = xp + (size_t)c * Hin * Win;
#pragma unroll
            for (int ky = 0; ky < 4; ky++) {
                if (!oky[ky]) continue;
                const float* xr = xc + iy[ky] * Win;
#pragma unroll
                for (int kx = 0; kx < 4; kx++) {
                    float v0 = okA[kx] ? __ldg(&xr[ixA[kx]]) : 0.f;
                    float v1 = okB[kx] ? __ldg(&xr[ixB[kx]]) : 0.f;
                    ull v0d = pack2(v0, v0);
                    ull v1d = pack2(v1, v1);
                    const ull* wp = (const ull*)&wsm[c][ky * 4 + kx][0];
#pragma unroll
                    for (int j = 0; j < 4; j++) {
                        ull wj = wp[j];
                        ffma2(acc[0][j], v0d, wj);
                        ffma2(acc[1][j], v1d, wj);
                    }
                }
            }
        }
    }

#pragma unroll
    for (int p = 0; p < 2; p++) {
        int ox = ox0 + 16 * p;
        if (ox >= Wout) continue;
#pragma unroll
        for (int j = 0; j < 4; j++) {
            float2 r = unpack2(acc[p][j]);
            int oc = oc0 + 2 * j;
            if (oc < Cout) {
                float v = r.x + bias[oc];
                if (relu) v = fmaxf(v, 0.f);
                y[(((size_t)n * Cout + oc) * Hout + oy) * Wout + ox] = v;
            }
            if (oc + 1 < Cout) {
                float v = r.y + bias[oc + 1];
                if (relu) v = fmaxf(v, 0.f);
                y[(((size_t)n * Cout + oc + 1) * Hout + oy) * Wout + ox] = v;
            }
        }
    }
}

// ---------------------------------------------------------------------------
// Transposed conv k=4 s=2 p=1, 4 pixels/thread.  Tile 64x16, 8 oc.
// Per output pixel exactly 2x2 taps; pixel p at ox0+16p -> pre-shift +16p.
// ---------------------------------------------------------------------------
__global__ __launch_bounds__(256)
void deconv_k4s2_p4(const float* __restrict__ x, const float* __restrict__ w,
                    const float* __restrict__ bias, float* __restrict__ y,
                    int N, int Cin, int Cout, int Hin, int Win, int relu)
{
    const int Hout = Hin << 1, Wout = Win << 1;
    const int ng = (Cout + 7) >> 3;
    const int n  = blockIdx.z / ng;
    const int oc0 = (blockIdx.z % ng) << 3;
    const int ox0 = blockIdx.x * 64 + threadIdx.x;
    const int oy  = blockIdx.y * 16 + threadIdx.y;
    const int tid = threadIdx.y * 16 + threadIdx.x;

    const int pr = oy & 1, q = ox0 & 1;
    int rofs[2], tapy[2]; bool vy[2];
    int ix[2][4], tapx[2]; bool vx[2][4];   // [a][pixel]
#pragma unroll
    for (int a = 0; a < 2; a++) {
        int ky = pr + 2 * a; int t = oy + ky - 2;
        rofs[a] = (t >> 1) * Win;
        vy[a] = (t >= 0) && ((t >> 1) < Hin);
        tapy[a] = ky;
        int kx = q + 2 * a;
        tapx[a] = kx;
#pragma unroll
        for (int p = 0; p < 4; p++) {
            int s = ox0 + kx - 2 + 16 * p;   // +16 out pixels -> +16 pre-shift
            ix[a][p] = s >> 1;
            vx[a][p] = (s >= 0) && ((s >> 1) < Win);
        }
    }

    __shared__ float wsm[64][16][8];

    ull acc[4][4];
#pragma unroll
    for (int p = 0; p < 4; p++)
#pragma unroll
        for (int j = 0; j < 4; j++) acc[p][j] = 0ull;

    for (int ic0 = 0; ic0 < Cin; ic0 += 64) {
        const int icc = min(64, Cin - ic0);
        __syncthreads();
        for (int i = tid; i < icc * 128; i += 256) {
            int c = i >> 7, rem = i & 127, t = rem >> 3, o = rem & 7;
            float wv = 0.f;
            if (oc0 + o < Cout)
                wv = w[(((oc0 + o) * Cin + ic0 + c) << 4) + t];
            wsm[c][t][o] = wv;
        }
        __syncthreads();

        const float* xp = x + ((size_t)(n * Cin + ic0) * Hin) * Win;
        for (int c = 0; c < icc; c++) {
            const float* xc = xp + (size_t)c * Hin * Win;
#pragma unroll
            for (int a = 0; a < 2; a++) {
                if (!vy[a]) continue;
                const float* xr = xc + rofs[a];
#pragma unroll
                for (int b2 = 0; b2 < 2; b2++) {
                    ull vd[4];
#pragma unroll
                    for (int p = 0; p < 4; p++) {
                        float v = vx[b2][p] ? __ldg(&xr[ix[b2][p]]) : 0.f;
                        vd[p] = pack2(v, v);
                    }
                    const ull* wp = (const ull*)&wsm[c][tapy[a] * 4 + tapx[b2]][0];
#pragma unroll
                    for (int j = 0; j < 4; j++) {
                        ull wj = wp[j];
#pragma unroll
                        for (int p = 0; p < 4; p++)
                            ffma2(acc[p][j], vd[p], wj);
                    }
                }
            }
        }
    }

#pragma unroll
    for (int p = 0; p < 4; p++) {
        int ox = ox0 + 16 * p;
        if (ox >= Wout) continue;
#pragma unroll
        for (int j = 0; j < 4; j++) {
            float2 r = unpack2(acc[p][j]);
            int oc = oc0 + 2 * j;
            if (oc < Cout) {
                float v = r.x + bias[oc];
                if (relu) v = fmaxf(v, 0.f);
                y[(((size_t)n * Cout + oc) * Hout + oy) * Wout + ox] = v;
            }
            if (oc + 1 < Cout) {
                float v = r.y + bias[oc + 1];
                if (relu) v = fmaxf(v, 0.f);
                y[(((size_t)n * Cout + oc + 1) * Hout + oy) * Wout + ox] = v;
            }
        }
    }
}

// ---------------------------------------------------------------------------
// feat [B,256,32,32] -> tok [B*1024, 256]
// ---------------------------------------------------------------------------
__global__ __launch_bounds__(1024)
void transpose_feat(const float* __restrict__ feat, float* __restrict__ tok)
{
    __shared__ float sm[32][33];
    const int hw0 = blockIdx.x * 32, c0 = blockIdx.y * 32, b = blockIdx.z;
    const int tx = threadIdx.x, ty = threadIdx.y;
    sm[ty][tx] = feat[((size_t)(b * 256 + c0 + ty)) * 1024 + hw0 + tx];
    __syncthreads();
    tok[((size_t)(b * 1024 + hw0 + ty)) * 256 + c0 + tx] = sm[tx][ty];
}

// ---------------------------------------------------------------------------
// Argmax GEMM (R4, verified): As persistent, Bs double-buffered.
// ---------------------------------------------------------------------------
#define AS_STRIDE 258
#define BS_STRIDE 66
#define GEMM_SMEM_BYTES ((64*AS_STRIDE + 2*64*BS_STRIDE + 64*16) * 4 + 64*16*4)

__global__ __launch_bounds__(256)
void argmax_gemm(const float* __restrict__ tok, const float* __restrict__ cb,
                 float* __restrict__ pv, int* __restrict__ pi)
{
    extern __shared__ float dyn[];
    float (*As)[AS_STRIDE] = (float (*)[AS_STRIDE])dyn;
    float (*Bs)[64][BS_STRIDE] = (float (*)[64][BS_STRIDE])(dyn + 64 * AS_STRIDE);
    float (*rv)[16] = (float (*)[16])(dyn + 64 * AS_STRIDE + 2 * 64 * BS_STRIDE);
    int   (*ri)[16] = (int   (*)[16])(dyn + 64 * AS_STRIDE + 2 * 64 * BS_STRIDE + 64 * 16);

    const int tid = threadIdx.x;
    const int e = tid & 15, f = tid >> 4;
    const int t0 = (blockIdx.x >> 1) * 64;
    const int half = blockIdx.x & 1;
    const int jhalf0 = half * 4096;

    const int fr  = tid >> 2;
    const int fcs = (tid & 3) << 4;
    const int fca = (tid & 3) << 6;

    {
        const float4* src = (const float4*)&tok[(size_t)(t0 + fr) * 256 + fca];
#pragma unroll
        for (int u = 0; u < 16; u++) {
            float4 v = src[u];
            float* d = &As[fr][fca + 4 * u];
            *(float2*)&d[0] = make_float2(v.x, v.y);
            *(float2*)&d[2] = make_float2(v.z, v.w);
        }
    }

    float4 pre[4];
    {
        const float4* src = (const float4*)&cb[(size_t)(jhalf0 + fr) * 256 + fcs];
#pragma unroll
        for (int u = 0; u < 4; u++) pre[u] = src[u];
        float* d = &Bs[0][fr][fcs];
#pragma unroll
        for (int u = 0; u < 4; u++) {
            *(float2*)&d[4 * u]     = make_float2(pre[u].x, pre[u].y);
            *(float2*)&d[4 * u + 2] = make_float2(pre[u].z, pre[u].w);
        }
    }
    __syncthreads();

    float bv[4]; int bi[4];
#pragma unroll
    for (int m = 0; m < 4; m++) { bv[m] = -INFINITY; bi[m] = 0; }

    ull cacc[4][4];

    for (int s = 0; s < 256; s++) {
        const int buf = s & 1;
        const int k0 = (s & 3) << 6;

        if ((s & 3) == 0) {
#pragma unroll
            for (int m = 0; m < 4; m++)
#pragma unroll
                for (int nn = 0; nn < 4; nn++) cacc[m][nn] = 0ull;
        }

        if (s < 255) {
            const int s1 = s + 1;
            const int jb = jhalf0 + (s1 >> 2) * 64;
            const int k1 = (s1 & 3) << 6;
            const float4* src = (const float4*)&cb[(size_t)(jb + fr) * 256 + k1 + fcs];
#pragma unroll
            for (int u = 0; u < 4; u++) pre[u] = src[u];
        }

#pragma unroll 8
        for (int kk = 0; kk < 32; kk++) {
            const int ka = k0 + 2 * kk;
            const int kb = 2 * kk;
            ull a2[4], b2[4];
#pragma unroll
            for (int m = 0; m < 4; m++)
                a2[m] = *(const ull*)&As[e + 16 * m][ka];
#pragma unroll
            for (int nn = 0; nn < 4; nn++)
                b2[nn] = *(const ull*)&Bs[buf][f + 16 * nn][kb];
#pragma unroll
            for (int m = 0; m < 4; m++)
#pragma unroll
                for (int nn = 0; nn < 4; nn++)
                    ffma2(cacc[m][nn], a2[m], b2[nn]);
        }

        if ((s & 3) == 3) {
            const int jbase = jhalf0 + (s >> 2) * 64;
#pragma unroll
            for (int m = 0; m < 4; m++)
#pragma unroll
                for (int nn = 0; nn < 4; nn++) {
                    float2 sv = unpack2(cacc[m][nn]);
                    float v = sv.x + sv.y;
                    int j = jbase + f + 16 * nn;
                    if (v > bv[m] || (v == bv[m] && j < bi[m])) { bv[m] = v; bi[m] = j; }
                }
        }

        if (s < 255) {
            float* d = &Bs[(s + 1) & 1][fr][fcs];
#pragma unroll
            for (int u = 0; u < 4; u++) {
                *(float2*)&d[4 * u]     = make_float2(pre[u].x, pre[u].y);
                *(float2*)&d[4 * u + 2] = make_float2(pre[u].z, pre[u].w);
            }
        }
        __syncthreads();
    }

#pragma unroll
    for (int m = 0; m < 4; m++) { rv[e + 16 * m][f] = bv[m]; ri[e + 16 * m][f] = bi[m]; }
    __syncthreads();
    if (tid < 64) {
        float best = rv[tid][0]; int bidx = ri[tid][0];
#pragma unroll
        for (int g = 1; g < 16; g++) {
            float v = rv[tid][g]; int j = ri[tid][g];
            if (v > best || (v == best && j < bidx)) { best = v; bidx = j; }
        }
        pv[half * (B * 1024) + t0 + tid] = best;
        pi[half * (B * 1024) + t0 + tid] = bidx;
    }
}

__global__ void merge_idx(const float* __restrict__ pv, const int* __restrict__ pi,
                          int* __restrict__ idx)
{
    int t = blockIdx.x * 256 + threadIdx.x;
    if (t >= B * 1024) return;
    float v0 = pv[t], v1 = pv[B * 1024 + t];
    idx[t] = (v1 > v0) ? pi[B * 1024 + t] : pi[t];   // half 0 wins ties (lower j)
}

__global__ __launch_bounds__(1024)
void gather_q(const float* __restrict__ cb, const int* __restrict__ idx,
              float* __restrict__ q)
{
    __shared__ float sm[32][33];
    __shared__ int rows[32];
    const int hw0 = blockIdx.x * 32, c0 = blockIdx.y * 32, b = blockIdx.z;
    const int tx = threadIdx.x, ty = threadIdx.y;
    if (ty == 0) rows[tx] = idx[b * 1024 + hw0 + tx];
    __syncthreads();
    sm[ty][tx] = cb[(size_t)rows[ty] * 256 + c0 + tx];
    __syncthreads();
    q[((size_t)(b * 256 + c0 + ty)) * 1024 + hw0 + tx] = sm[tx][ty];
}

__global__ void idx_to_float(const int* __restrict__ idx, float* __restrict__ out)
{
    int t = blockIdx.x * 256 + threadIdx.x;
    if (t < B * 1024) out[t] = (float)idx[t];
}

// ---------------------------------------------------------------------------
// Launch
// ---------------------------------------------------------------------------
extern "C" void kernel_launch(void* const* d_in, const int* in_sizes, int n_in,
                              void* d_out, int out_size)
{
    const float* x   = (const float*)d_in[0];
    const float* ew1 = (const float*)d_in[1];
    const float* eb1 = (const float*)d_in[2];
    const float* ew2 = (const float*)d_in[3];
    const float* eb2 = (const float*)d_in[4];
    const float* ew3 = (const float*)d_in[5];
    const float* eb3 = (const float*)d_in[6];
    const float* cb  = (const float*)d_in[7];
    const float* dw1 = (const float*)d_in[8];
    const float* db1 = (const float*)d_in[9];
    const float* dw2 = (const float*)d_in[10];
    const float* db2 = (const float*)d_in[11];
    const float* dw3 = (const float*)d_in[12];
    const float* db3 = (const float*)d_in[13];
    float* out = (float*)d_out;

    float *h1, *h2, *feat, *tok, *q, *d1, *d2, *pv;
    int *idxp, *pip;
    cudaGetSymbolAddress((void**)&h1,  g_h1);
    cudaGetSymbolAddress((void**)&h2,  g_h2);
    cudaGetSymbolAddress((void**)&feat,g_feat);
    cudaGetSymbolAddress((void**)&tok, g_tok);
    cudaGetSymbolAddress((void**)&q,   g_q);
    cudaGetSymbolAddress((void**)&d1,  g_d1);
    cudaGetSymbolAddress((void**)&d2,  g_d2);
    cudaGetSymbolAddress((void**)&idxp,g_idx);
    cudaGetSymbolAddress((void**)&pv,  g_pv);
    cudaGetSymbolAddress((void**)&pip, g_pi);

    static int smem_set = 0;
    if (!smem_set) {
        cudaFuncSetAttribute(argmax_gemm,
                             cudaFuncAttributeMaxDynamicSharedMemorySize,
                             GEMM_SMEM_BYTES);
        smem_set = 1;
    }

    dim3 b16(16, 16);

    // encoder: conv1/conv2 use 4-pixel tiles (64 wide); conv3 keeps 32-wide
    conv_k4s2_p4<<<dim3(2, 8, B * 8),  b16>>>(x,  ew1, eb1, h1,   B,   3,  64, 256, 256, 1);
    conv_k4s2_p4<<<dim3(1, 4, B * 16), b16>>>(h1, ew2, eb2, h2,   B,  64, 128, 128, 128, 1);
    conv_k4s2   <<<dim3(1, 2, B * 32), b16>>>(h2, ew3, eb3, feat, B, 128, 256,  64,  64, 0);

    // quantize
    transpose_feat<<<dim3(32, 8, B), dim3(32, 32)>>>(feat, tok);
    argmax_gemm<<<(B * 1024 / 64) * 2, 256, GEMM_SMEM_BYTES>>>(tok, cb, pv, pip);
    merge_idx<<<(B * 1024 + 255) / 256, 256>>>(pv, pip, idxp);
    gather_q<<<dim3(32, 8, B), dim3(32, 32)>>>(cb, idxp, q);

    // decoder: all 4-pixel tiles (64 wide)
    deconv_k4s2_p4<<<dim3(1, 4, B * 16), b16>>>(q,  dw1, db1, d1, B, 256, 128, 32, 32, 1);
    deconv_k4s2_p4<<<dim3(2, 8, B * 8),  b16>>>(d1, dw2, db2, d2, B, 128,  64, 64, 64, 1);
    deconv_k4s2_p4<<<dim3(4, 16, B),     b16>>>(d2, dw3, db3, out, B, 64,   3, 128, 128, 0);

    const int recon_elems = B * 3 * 256 * 256;
    if (out_size >= recon_elems + B * 1024)
        idx_to_float<<<(B * 1024 + 255) / 256, 256>>>(idxp, out + recon_elems);
}

// round 7
// speedup vs baseline: 1.0954x; 1.0954x over previous
#include <cuda_runtime.h>
#include <cuda_bf16.h>
#include <math.h>

#define B 16
typedef unsigned long long ull;

// ---------------------------------------------------------------------------
// f32x2 packed helpers (Blackwell dual-fp32 pipe)
// ---------------------------------------------------------------------------
__device__ __forceinline__ void ffma2(ull &acc, ull a, ull b) {
    asm("fma.rn.f32x2 %0, %1, %2, %0;" : "+l"(acc) : "l"(a), "l"(b));
}
__device__ __forceinline__ ull pack2(float a, float b) {
    ull r; asm("mov.b64 %0, {%1, %2};" : "=l"(r) : "f"(a), "f"(b)); return r;
}
__device__ __forceinline__ float2 unpack2(ull v) {
    float2 r; asm("mov.b64 {%0, %1}, %2;" : "=f"(r.x), "=f"(r.y) : "l"(v)); return r;
}

// ---------------------------------------------------------------------------
// Scratch (device globals; no allocation allowed)
// ---------------------------------------------------------------------------
__device__ float g_h1[B*64*128*128];
__device__ float g_h2[B*128*64*64];
__device__ float g_feat[B*256*32*32];
__device__ float g_tok[B*1024*256];
__device__ float g_q[B*256*32*32];
__device__ float g_d1[B*128*64*64];
__device__ float g_d2[B*64*128*128];
__device__ int   g_idx[B*1024];
__device__ float g_pv[2*B*1024];
__device__ int   g_pi[2*B*1024];

// ---------------------------------------------------------------------------
// Direct conv k=4 s=2 p=1, 16 oc per block, 2 pixels/thread.  Tile 32x16.
// Per tap: 2 LDG + 2 pack + 8 LDS.64 + 16 FFMA2 -> fp-pipe bound.
// Weight smem chunked 32 channels (32 KB).
// ---------------------------------------------------------------------------
__global__ __launch_bounds__(256, 2)
void conv_k4s2_oc16(const float* __restrict__ x, const float* __restrict__ w,
                    const float* __restrict__ bias, float* __restrict__ y,
                    int N, int Cin, int Cout, int Hin, int Win, int relu)
{
    const int Hout = Hin >> 1, Wout = Win >> 1;
    const int ng = (Cout + 15) >> 4;
    const int n  = blockIdx.z / ng;
    const int oc0 = (blockIdx.z % ng) << 4;
    const int ox0 = blockIdx.x * 32 + threadIdx.x;
    const int oy  = blockIdx.y * 16 + threadIdx.y;
    const int tid = threadIdx.y * 16 + threadIdx.x;

    __shared__ float wsm[32][16][16];   // [ic][tap][oc] : 32 KB

    int iy[4]; bool oky[4];
    int ixA[4], ixB[4]; bool okA[4], okB[4];
#pragma unroll
    for (int k = 0; k < 4; k++) {
        int t = oy * 2 + k - 1;
        iy[k] = t; oky[k] = (unsigned)t < (unsigned)Hin;
        int sA = ox0 * 2 + k - 1;
        ixA[k] = sA; okA[k] = (unsigned)sA < (unsigned)Win;
        int sB = sA + 32;                      // +16 out -> +32 in
        ixB[k] = sB; okB[k] = (unsigned)sB < (unsigned)Win;
    }

    ull acc[2][8];
#pragma unroll
    for (int p = 0; p < 2; p++)
#pragma unroll
        for (int j = 0; j < 8; j++) acc[p][j] = 0ull;

    for (int ic0 = 0; ic0 < Cin; ic0 += 32) {
        const int icc = min(32, Cin - ic0);
        __syncthreads();
        for (int i = tid; i < icc * 256; i += 256) {
            int c = i >> 8, rem = i & 255, t = rem >> 4, o = rem & 15;
            float wv = 0.f;
            if (oc0 + o < Cout)
                wv = w[(((oc0 + o) * Cin + ic0 + c) << 4) + t];
            wsm[c][t][o] = wv;
        }
        __syncthreads();

        const float* xp = x + ((size_t)(n * Cin + ic0) * Hin) * Win;
        for (int c = 0; c < icc; c++) {
            const float* xc = xp + (size_t)c * Hin * Win;
#pragma unroll
            for (int ky = 0; ky < 4; ky++) {
                if (!oky[ky]) continue;
                const float* xr = xc + iy[ky] * Win;
#pragma unroll
                for (int kx = 0; kx < 4; kx++) {
                    float v0 = okA[kx] ? __ldg(&xr[ixA[kx]]) : 0.f;
                    float v1 = okB[kx] ? __ldg(&xr[ixB[kx]]) : 0.f;
                    ull v0d = pack2(v0, v0);
                    ull v1d = pack2(v1, v1);
                    const ull* wp = (const ull*)&wsm[c][ky * 4 + kx][0];
#pragma unroll
                    for (int j = 0; j < 8; j++) {
                        ull wj = wp[j];
                        ffma2(acc[0][j], v0d, wj);
                        ffma2(acc[1][j], v1d, wj);
                    }
                }
            }
        }
    }

#pragma unroll
    for (int p = 0; p < 2; p++) {
        int ox = ox0 + 16 * p;
        if (ox >= Wout) continue;
#pragma unroll
        for (int j = 0; j < 8; j++) {
            float2 r = unpack2(acc[p][j]);
            int oc = oc0 + 2 * j;
            if (oc < Cout) {
                float v = r.x + bias[oc];
                if (relu) v = fmaxf(v, 0.f);
                y[(((size_t)n * Cout + oc) * Hout + oy) * Wout + ox] = v;
            }
            if (oc + 1 < Cout) {
                float v = r.y + bias[oc + 1];
                if (relu) v = fmaxf(v, 0.f);
                y[(((size_t)n * Cout + oc + 1) * Hout + oy) * Wout + ox] = v;
            }
        }
    }
}

// ---------------------------------------------------------------------------
// Transposed conv k=4 s=2 p=1, 16 oc per block, 2 pixels/thread.
// Per output pixel exactly 2x2 taps (parity-selected).
// ---------------------------------------------------------------------------
__global__ __launch_bounds__(256, 2)
void deconv_k4s2_oc16(const float* __restrict__ x, const float* __restrict__ w,
                      const float* __restrict__ bias, float* __restrict__ y,
                      int N, int Cin, int Cout, int Hin, int Win, int relu)
{
    const int Hout = Hin << 1, Wout = Win << 1;
    const int ng = (Cout + 15) >> 4;
    const int n  = blockIdx.z / ng;
    const int oc0 = (blockIdx.z % ng) << 4;
    const int ox0 = blockIdx.x * 32 + threadIdx.x;
    const int oy  = blockIdx.y * 16 + threadIdx.y;
    const int tid = threadIdx.y * 16 + threadIdx.x;

    const int pr = oy & 1, q = ox0 & 1;
    int rofs[2], tapy[2]; bool vy[2];
    int ixA[2], ixB[2], tapx[2]; bool vA[2], vB[2];
#pragma unroll
    for (int a = 0; a < 2; a++) {
        int ky = pr + 2 * a; int t = oy + ky - 2;
        rofs[a] = (t >> 1) * Win;
        vy[a] = (t >= 0) && ((t >> 1) < Hin);
        tapy[a] = ky;
        int kx = q + 2 * a;
        int sA = ox0 + kx - 2;
        ixA[a] = sA >> 1; vA[a] = (sA >= 0) && ((sA >> 1) < Win);
        int sB = sA + 16;                       // +16 out -> +16 pre-shift
        ixB[a] = sB >> 1; vB[a] = (sB >= 0) && ((sB >> 1) < Win);
        tapx[a] = kx;
    }

    __shared__ float wsm[32][16][16];

    ull acc[2][8];
#pragma unroll
    for (int pp = 0; pp < 2; pp++)
#pragma unroll
        for (int j = 0; j < 8; j++) acc[pp][j] = 0ull;

    for (int ic0 = 0; ic0 < Cin; ic0 += 32) {
        const int icc = min(32, Cin - ic0);
        __syncthreads();
        for (int i = tid; i < icc * 256; i += 256) {
            int c = i >> 8, rem = i & 255, t = rem >> 4, o = rem & 15;
            float wv = 0.f;
            if (oc0 + o < Cout)
                wv = w[(((oc0 + o) * Cin + ic0 + c) << 4) + t];
            wsm[c][t][o] = wv;
        }
        __syncthreads();

        const float* xp = x + ((size_t)(n * Cin + ic0) * Hin) * Win;
        for (int c = 0; c < icc; c++) {
            const float* xc = xp + (size_t)c * Hin * Win;
#pragma unroll
            for (int a = 0; a < 2; a++) {
                if (!vy[a]) continue;
                const float* xr = xc + rofs[a];
#pragma unroll
                for (int b2 = 0; b2 < 2; b2++) {
                    float v0 = vA[b2] ? __ldg(&xr[ixA[b2]]) : 0.f;
                    float v1 = vB[b2] ? __ldg(&xr[ixB[b2]]) : 0.f;
                    ull v0d = pack2(v0, v0);
                    ull v1d = pack2(v1, v1);
                    const ull* wp = (const ull*)&wsm[c][tapy[a] * 4 + tapx[b2]][0];
#pragma unroll
                    for (int j = 0; j < 8; j++) {
                        ull wj = wp[j];
                        ffma2(acc[0][j], v0d, wj);
                        ffma2(acc[1][j], v1d, wj);
                    }
                }
            }
        }
    }

#pragma unroll
    for (int pp = 0; pp < 2; pp++) {
        int ox = ox0 + 16 * pp;
        if (ox >= Wout) continue;
#pragma unroll
        for (int j = 0; j < 8; j++) {
            float2 r = unpack2(acc[pp][j]);
            int oc = oc0 + 2 * j;
            if (oc < Cout) {
                float v = r.x + bias[oc];
                if (relu) v = fmaxf(v, 0.f);
                y[(((size_t)n * Cout + oc) * Hout + oy) * Wout + ox] = v;
            }
            if (oc + 1 < Cout) {
                float v = r.y + bias[oc + 1];
                if (relu) v = fmaxf(v, 0.f);
                y[(((size_t)n * Cout + oc + 1) * Hout + oy) * Wout + ox] = v;
            }
        }
    }
}

// ---------------------------------------------------------------------------
// R4 8-oc deconv (verified) — used for deconv3 (Cout=3).
// ---------------------------------------------------------------------------
__global__ __launch_bounds__(256)
void deconv_k4s2(const float* __restrict__ x, const float* __restrict__ w,
                 const float* __restrict__ bias, float* __restrict__ y,
                 int N, int Cin, int Cout, int Hin, int Win, int relu)
{
    const int Hout = Hin << 1, Wout = Win << 1;
    const int ng = (Cout + 7) >> 3;
    const int n  = blockIdx.z / ng;
    const int oc0 = (blockIdx.z % ng) << 3;
    const int ox0 = blockIdx.x * 32 + threadIdx.x;
    const int oy  = blockIdx.y * 16 + threadIdx.y;
    const int tid = threadIdx.y * 16 + threadIdx.x;

    const int p = oy & 1, q = ox0 & 1;
    int iyv[2], tapy[2]; bool vy[2];
    int ixA[2], ixB[2], tapx[2]; bool vA[2], vB[2];
#pragma unroll
    for (int a = 0; a < 2; a++) {
        int ky = p + 2 * a; int t = oy + ky - 2;
        iyv[a] = t >> 1; vy[a] = (t >= 0) && ((t >> 1) < Hin); tapy[a] = ky;
        int kx = q + 2 * a;
        int sA = ox0 + kx - 2;
        ixA[a] = sA >> 1; vA[a] = (sA >= 0) && ((sA >> 1) < Win);
        int sB = sA + 16;
        ixB[a] = sB >> 1; vB[a] = (sB >= 0) && ((sB >> 1) < Win);
        tapx[a] = kx;
    }

    __shared__ float wsm[64][16][8];

    ull acc[2][4];
#pragma unroll
    for (int pp = 0; pp < 2; pp++)
#pragma unroll
        for (int j = 0; j < 4; j++) acc[pp][j] = 0ull;

    for (int ic0 = 0; ic0 < Cin; ic0 += 64) {
        const int icc = min(64, Cin - ic0);
        __syncthreads();
        for (int i = tid; i < icc * 128; i += 256) {
            int c = i >> 7, rem = i & 127, t = rem >> 3, o = rem & 7;
            float wv = 0.f;
            if (oc0 + o < Cout)
                wv = w[(((oc0 + o) * Cin + ic0 + c) << 4) + t];
            wsm[c][t][o] = wv;
        }
        __syncthreads();

        const float* xp = x + ((size_t)(n * Cin + ic0) * Hin) * Win;
        for (int c = 0; c < icc; c++) {
            const float* xc = xp + (size_t)c * Hin * Win;
#pragma unroll
            for (int a = 0; a < 2; a++) {
                if (!vy[a]) continue;
                const float* xr = xc + iyv[a] * Win;
#pragma unroll
                for (int b2 = 0; b2 < 2; b2++) {
                    float v0 = vA[b2] ? __ldg(&xr[ixA[b2]]) : 0.f;
                    float v1 = vB[b2] ? __ldg(&xr[ixB[b2]]) : 0.f;
                    ull v0d = pack2(v0, v0);
                    ull v1d = pack2(v1, v1);
                    const ull* wp = (const ull*)&wsm[c][tapy[a] * 4 + tapx[b2]][0];
#pragma unroll
                    for (int j = 0; j < 4; j++) {
                        ull wj = wp[j];
                        ffma2(acc[0][j], v0d, wj);
                        ffma2(acc[1][j], v1d, wj);
                    }
                }
            }
        }
    }

#pragma unroll
    for (int pp = 0; pp < 2; pp++) {
        int ox = ox0 + 16 * pp;
        if (ox >= Wout) continue;
#pragma unroll
        for (int j = 0; j < 4; j++) {
            float2 r = unpack2(acc[pp][j]);
            int oc = oc0 + 2 * j;
            if (oc < Cout) {
                float v = r.x + bias[oc];
                if (relu) v = fmaxf(v, 0.f);
                y[(((size_t)n * Cout + oc) * Hout + oy) * Wout + ox] = v;
            }
            if (oc + 1 < Cout) {
                float v = r.y + bias[oc + 1];
                if (relu) v = fmaxf(v, 0.f);
                y[(((size_t)n * Cout + oc + 1) * Hout + oy) * Wout + ox] = v;
            }
        }
    }
}

// ---------------------------------------------------------------------------
// feat [B,256,32,32] -> tok [B*1024, 256]
// ---------------------------------------------------------------------------
__global__ __launch_bounds__(1024)
void transpose_feat(const float* __restrict__ feat, float* __restrict__ tok)
{
    __shared__ float sm[32][33];
    const int hw0 = blockIdx.x * 32, c0 = blockIdx.y * 32, b = blockIdx.z;
    const int tx = threadIdx.x, ty = threadIdx.y;
    sm[ty][tx] = feat[((size_t)(b * 256 + c0 + ty)) * 1024 + hw0 + tx];
    __syncthreads();
    tok[((size_t)(b * 1024 + hw0 + ty)) * 256 + c0 + tx] = sm[tx][ty];
}

// ---------------------------------------------------------------------------
// Argmax GEMM (R4, verified): As persistent, Bs double-buffered.
// ---------------------------------------------------------------------------
#define AS_STRIDE 258
#define BS_STRIDE 66
#define GEMM_SMEM_BYTES ((64*AS_STRIDE + 2*64*BS_STRIDE + 64*16) * 4 + 64*16*4)

__global__ __launch_bounds__(256)
void argmax_gemm(const float* __restrict__ tok, const float* __restrict__ cb,
                 float* __restrict__ pv, int* __restrict__ pi)
{
    extern __shared__ float dyn[];
    float (*As)[AS_STRIDE] = (float (*)[AS_STRIDE])dyn;
    float (*Bs)[64][BS_STRIDE] = (float (*)[64][BS_STRIDE])(dyn + 64 * AS_STRIDE);
    float (*rv)[16] = (float (*)[16])(dyn + 64 * AS_STRIDE + 2 * 64 * BS_STRIDE);
    int   (*ri)[16] = (int   (*)[16])(dyn + 64 * AS_STRIDE + 2 * 64 * BS_STRIDE + 64 * 16);

    const int tid = threadIdx.x;
    const int e = tid & 15, f = tid >> 4;
    const int t0 = (blockIdx.x >> 1) * 64;
    const int half = blockIdx.x & 1;
    const int jhalf0 = half * 4096;

    const int fr  = tid >> 2;
    const int fcs = (tid & 3) << 4;
    const int fca = (tid & 3) << 6;

    {
        const float4* src = (const float4*)&tok[(size_t)(t0 + fr) * 256 + fca];
#pragma unroll
        for (int u = 0; u < 16; u++) {
            float4 v = src[u];
            float* d = &As[fr][fca + 4 * u];
            *(float2*)&d[0] = make_float2(v.x, v.y);
            *(float2*)&d[2] = make_float2(v.z, v.w);
        }
    }

    float4 pre[4];
    {
        const float4* src = (const float4*)&cb[(size_t)(jhalf0 + fr) * 256 + fcs];
#pragma unroll
        for (int u = 0; u < 4; u++) pre[u] = src[u];
        float* d = &Bs[0][fr][fcs];
#pragma unroll
        for (int u = 0; u < 4; u++) {
            *(float2*)&d[4 * u]     = make_float2(pre[u].x, pre[u].y);
            *(float2*)&d[4 * u + 2] = make_float2(pre[u].z, pre[u].w);
        }
    }
    __syncthreads();

    float bv[4]; int bi[4];
#pragma unroll
    for (int m = 0; m < 4; m++) { bv[m] = -INFINITY; bi[m] = 0; }

    ull cacc[4][4];

    for (int s = 0; s < 256; s++) {
        const int buf = s & 1;
        const int k0 = (s & 3) << 6;

        if ((s & 3) == 0) {
#pragma unroll
            for (int m = 0; m < 4; m++)
#pragma unroll
                for (int nn = 0; nn < 4; nn++) cacc[m][nn] = 0ull;
        }

        if (s < 255) {
            const int s1 = s + 1;
            const int jb = jhalf0 + (s1 >> 2) * 64;
            const int k1 = (s1 & 3) << 6;
            const float4* src = (const float4*)&cb[(size_t)(jb + fr) * 256 + k1 + fcs];
#pragma unroll
            for (int u = 0; u < 4; u++) pre[u] = src[u];
        }

#pragma unroll 8
        for (int kk = 0; kk < 32; kk++) {
            const int ka = k0 + 2 * kk;
            const int kb = 2 * kk;
            ull a2[4], b2[4];
#pragma unroll
            for (int m = 0; m < 4; m++)
                a2[m] = *(const ull*)&As[e + 16 * m][ka];
#pragma unroll
            for (int nn = 0; nn < 4; nn++)
                b2[nn] = *(const ull*)&Bs[buf][f + 16 * nn][kb];
#pragma unroll
            for (int m = 0; m < 4; m++)
#pragma unroll
                for (int nn = 0; nn < 4; nn++)
                    ffma2(cacc[m][nn], a2[m], b2[nn]);
        }

        if ((s & 3) == 3) {
            const int jbase = jhalf0 + (s >> 2) * 64;
#pragma unroll
            for (int m = 0; m < 4; m++)
#pragma unroll
                for (int nn = 0; nn < 4; nn++) {
                    float2 sv = unpack2(cacc[m][nn]);
                    float v = sv.x + sv.y;
                    int j = jbase + f + 16 * nn;
                    if (v > bv[m] || (v == bv[m] && j < bi[m])) { bv[m] = v; bi[m] = j; }
                }
        }

        if (s < 255) {
            float* d = &Bs[(s + 1) & 1][fr][fcs];
#pragma unroll
            for (int u = 0; u < 4; u++) {
                *(float2*)&d[4 * u]     = make_float2(pre[u].x, pre[u].y);
                *(float2*)&d[4 * u + 2] = make_float2(pre[u].z, pre[u].w);
            }
        }
        __syncthreads();
    }

#pragma unroll
    for (int m = 0; m < 4; m++) { rv[e + 16 * m][f] = bv[m]; ri[e + 16 * m][f] = bi[m]; }
    __syncthreads();
    if (tid < 64) {
        float best = rv[tid][0]; int bidx = ri[tid][0];
#pragma unroll
        for (int g = 1; g < 16; g++) {
            float v = rv[tid][g]; int j = ri[tid][g];
            if (v > best || (v == best && j < bidx)) { best = v; bidx = j; }
        }
        pv[half * (B * 1024) + t0 + tid] = best;
        pi[half * (B * 1024) + t0 + tid] = bidx;
    }
}

__global__ void merge_idx(const float* __restrict__ pv, const int* __restrict__ pi,
                          int* __restrict__ idx)
{
    int t = blockIdx.x * 256 + threadIdx.x;
    if (t >= B * 1024) return;
    float v0 = pv[t], v1 = pv[B * 1024 + t];
    idx[t] = (v1 > v0) ? pi[B * 1024 + t] : pi[t];   // half 0 wins ties (lower j)
}

__global__ __launch_bounds__(1024)
void gather_q(const float* __restrict__ cb, const int* __restrict__ idx,
              float* __restrict__ q)
{
    __shared__ float sm[32][33];
    __shared__ int rows[32];
    const int hw0 = blockIdx.x * 32, c0 = blockIdx.y * 32, b = blockIdx.z;
    const int tx = threadIdx.x, ty = threadIdx.y;
    if (ty == 0) rows[tx] = idx[b * 1024 + hw0 + tx];
    __syncthreads();
    sm[ty][tx] = cb[(size_t)rows[ty] * 256 + c0 + tx];
    __syncthreads();
    q[((size_t)(b * 256 + c0 + ty)) * 1024 + hw0 + tx] = sm[tx][ty];
}

__global__ void idx_to_float(const int* __restrict__ idx, float* __restrict__ out)
{
    int t = blockIdx.x * 256 + threadIdx.x;
    if (t < B * 1024) out[t] = (float)idx[t];
}

// ---------------------------------------------------------------------------
// Launch
// ---------------------------------------------------------------------------
extern "C" void kernel_launch(void* const* d_in, const int* in_sizes, int n_in,
                              void* d_out, int out_size)
{
    const float* x   = (const float*)d_in[0];
    const float* ew1 = (const float*)d_in[1];
    const float* eb1 = (const float*)d_in[2];
    const float* ew2 = (const float*)d_in[3];
    const float* eb2 = (const float*)d_in[4];
    const float* ew3 = (const float*)d_in[5];
    const float* eb3 = (const float*)d_in[6];
    const float* cb  = (const float*)d_in[7];
    const float* dw1 = (const float*)d_in[8];
    const float* db1 = (const float*)d_in[9];
    const float* dw2 = (const float*)d_in[10];
    const float* db2 = (const float*)d_in[11];
    const float* dw3 = (const float*)d_in[12];
    const float* db3 = (const float*)d_in[13];
    float* out = (float*)d_out;

    float *h1, *h2, *feat, *tok, *q, *d1, *d2, *pv;
    int *idxp, *pip;
    cudaGetSymbolAddress((void**)&h1,  g_h1);
    cudaGetSymbolAddress((void**)&h2,  g_h2);
    cudaGetSymbolAddress((void**)&feat,g_feat);
    cudaGetSymbolAddress((void**)&tok, g_tok);
    cudaGetSymbolAddress((void**)&q,   g_q);
    cudaGetSymbolAddress((void**)&d1,  g_d1);
    cudaGetSymbolAddress((void**)&d2,  g_d2);
    cudaGetSymbolAddress((void**)&idxp,g_idx);
    cudaGetSymbolAddress((void**)&pv,  g_pv);
    cudaGetSymbolAddress((void**)&pip, g_pi);

    static int smem_set = 0;
    if (!smem_set) {
        cudaFuncSetAttribute(argmax_gemm,
                             cudaFuncAttributeMaxDynamicSharedMemorySize,
                             GEMM_SMEM_BYTES);
        smem_set = 1;
    }

    dim3 b16(16, 16);

    // encoder: 16-oc blocks, 32x16 tiles
    conv_k4s2_oc16<<<dim3(4, 8, B * 4),  b16>>>(x,  ew1, eb1, h1,   B,   3,  64, 256, 256, 1);
    conv_k4s2_oc16<<<dim3(2, 4, B * 8),  b16>>>(h1, ew2, eb2, h2,   B,  64, 128, 128, 128, 1);
    conv_k4s2_oc16<<<dim3(1, 2, B * 16), b16>>>(h2, ew3, eb3, feat, B, 128, 256,  64,  64, 0);

    // quantize
    transpose_feat<<<dim3(32, 8, B), dim3(32, 32)>>>(feat, tok);
    argmax_gemm<<<(B * 1024 / 64) * 2, 256, GEMM_SMEM_BYTES>>>(tok, cb, pv, pip);
    merge_idx<<<(B * 1024 + 255) / 256, 256>>>(pv, pip, idxp);
    gather_q<<<dim3(32, 8, B), dim3(32, 32)>>>(cb, idxp, q);

    // decoder: deconv1/deconv2 16-oc; deconv3 (Cout=3) 8-oc
    deconv_k4s2_oc16<<<dim3(2, 4, B * 8), b16>>>(q,  dw1, db1, d1, B, 256, 128, 32, 32, 1);
    deconv_k4s2_oc16<<<dim3(4, 8, B * 4), b16>>>(d1, dw2, db2, d2, B, 128,  64, 64, 64, 1);
    deconv_k4s2    <<<dim3(8, 16, B),     b16>>>(d2, dw3, db3, out, B, 64,   3, 128, 128, 0);

    const int recon_elems = B * 3 * 256 * 256;
    if (out_size >= recon_elems + B * 1024)
        idx_to_float<<<(B * 1024 + 255) / 256, 256>>>(idxp, out + recon_elems);
}

// round 8
// speedup vs baseline: 1.1502x; 1.0500x over previous
#include <cuda_runtime.h>
#include <cuda_bf16.h>
#include <math.h>

#define B 16
typedef unsigned long long ull;

// ---------------------------------------------------------------------------
// f32x2 packed helpers (Blackwell dual-fp32 pipe)
// ---------------------------------------------------------------------------
__device__ __forceinline__ void ffma2(ull &acc, ull a, ull b) {
    asm("fma.rn.f32x2 %0, %1, %2, %0;" : "+l"(acc) : "l"(a), "l"(b));
}
__device__ __forceinline__ ull pack2(float a, float b) {
    ull r; asm("mov.b64 %0, {%1, %2};" : "=l"(r) : "f"(a), "f"(b)); return r;
}
__device__ __forceinline__ float2 unpack2(ull v) {
    float2 r; asm("mov.b64 {%0, %1}, %2;" : "=f"(r.x), "=f"(r.y) : "l"(v)); return r;
}

// ---------------------------------------------------------------------------
// Scratch (device globals; no allocation allowed)
// ---------------------------------------------------------------------------
__device__ float g_h1[B*64*128*128];
__device__ float g_h2[B*128*64*64];
__device__ float g_feat[B*256*32*32];
__device__ float g_tok[B*1024*256];
__device__ float g_q[B*256*32*32];
__device__ float g_d1[B*128*64*64];
__device__ float g_d2[B*64*128*128];
__device__ int   g_idx[B*1024];
__device__ float g_pv[2*B*1024];
__device__ int   g_pi[2*B*1024];

// ---------------------------------------------------------------------------
// Direct conv k=4 s=2 p=1, 16 oc per block, 2 pixels/thread (R7, verified).
// ---------------------------------------------------------------------------
__global__ __launch_bounds__(256, 2)
void conv_k4s2_oc16(const float* __restrict__ x, const float* __restrict__ w,
                    const float* __restrict__ bias, float* __restrict__ y,
                    int N, int Cin, int Cout, int Hin, int Win, int relu)
{
    const int Hout = Hin >> 1, Wout = Win >> 1;
    const int ng = (Cout + 15) >> 4;
    const int n  = blockIdx.z / ng;
    const int oc0 = (blockIdx.z % ng) << 4;
    const int ox0 = blockIdx.x * 32 + threadIdx.x;
    const int oy  = blockIdx.y * 16 + threadIdx.y;
    const int tid = threadIdx.y * 16 + threadIdx.x;

    __shared__ float wsm[32][16][16];

    int iy[4]; bool oky[4];
    int ixA[4], ixB[4]; bool okA[4], okB[4];
#pragma unroll
    for (int k = 0; k < 4; k++) {
        int t = oy * 2 + k - 1;
        iy[k] = t; oky[k] = (unsigned)t < (unsigned)Hin;
        int sA = ox0 * 2 + k - 1;
        ixA[k] = sA; okA[k] = (unsigned)sA < (unsigned)Win;
        int sB = sA + 32;
        ixB[k] = sB; okB[k] = (unsigned)sB < (unsigned)Win;
    }

    ull acc[2][8];
#pragma unroll
    for (int p = 0; p < 2; p++)
#pragma unroll
        for (int j = 0; j < 8; j++) acc[p][j] = 0ull;

    for (int ic0 = 0; ic0 < Cin; ic0 += 32) {
        const int icc = min(32, Cin - ic0);
        __syncthreads();
        for (int i = tid; i < icc * 256; i += 256) {
            int c = i >> 8, rem = i & 255, t = rem >> 4, o = rem & 15;
            float wv = 0.f;
            if (oc0 + o < Cout)
                wv = w[(((oc0 + o) * Cin + ic0 + c) << 4) + t];
            wsm[c][t][o] = wv;
        }
        __syncthreads();

        const float* xp = x + ((size_t)(n * Cin + ic0) * Hin) * Win;
        for (int c = 0; c < icc; c++) {
            const float* xc = xp + (size_t)c * Hin * Win;
#pragma unroll
            for (int ky = 0; ky < 4; ky++) {
                if (!oky[ky]) continue;
                const float* xr = xc + iy[ky] * Win;
#pragma unroll
                for (int kx = 0; kx < 4; kx++) {
                    float v0 = okA[kx] ? __ldg(&xr[ixA[kx]]) : 0.f;
                    float v1 = okB[kx] ? __ldg(&xr[ixB[kx]]) : 0.f;
                    ull v0d = pack2(v0, v0);
                    ull v1d = pack2(v1, v1);
                    const ull* wp = (const ull*)&wsm[c][ky * 4 + kx][0];
#pragma unroll
                    for (int j = 0; j < 8; j++) {
                        ull wj = wp[j];
                        ffma2(acc[0][j], v0d, wj);
                        ffma2(acc[1][j], v1d, wj);
                    }
                }
            }
        }
    }

#pragma unroll
    for (int p = 0; p < 2; p++) {
        int ox = ox0 + 16 * p;
        if (ox >= Wout) continue;
#pragma unroll
        for (int j = 0; j < 8; j++) {
            float2 r = unpack2(acc[p][j]);
            int oc = oc0 + 2 * j;
            if (oc < Cout) {
                float v = r.x + bias[oc];
                if (relu) v = fmaxf(v, 0.f);
                y[(((size_t)n * Cout + oc) * Hout + oy) * Wout + ox] = v;
            }
            if (oc + 1 < Cout) {
                float v = r.y + bias[oc + 1];
                if (relu) v = fmaxf(v, 0.f);
                y[(((size_t)n * Cout + oc + 1) * Hout + oy) * Wout + ox] = v;
            }
        }
    }
}

// ---------------------------------------------------------------------------
// Transposed conv k=4 s=2 p=1, 16 oc per block (R7, verified).
// ---------------------------------------------------------------------------
__global__ __launch_bounds__(256, 2)
void deconv_k4s2_oc16(const float* __restrict__ x, const float* __restrict__ w,
                      const float* __restrict__ bias, float* __restrict__ y,
                      int N, int Cin, int Cout, int Hin, int Win, int relu)
{
    const int Hout = Hin << 1, Wout = Win << 1;
    const int ng = (Cout + 15) >> 4;
    const int n  = blockIdx.z / ng;
    const int oc0 = (blockIdx.z % ng) << 4;
    const int ox0 = blockIdx.x * 32 + threadIdx.x;
    const int oy  = blockIdx.y * 16 + threadIdx.y;
    const int tid = threadIdx.y * 16 + threadIdx.x;

    const int pr = oy & 1, q = ox0 & 1;
    int rofs[2], tapy[2]; bool vy[2];
    int ixA[2], ixB[2], tapx[2]; bool vA[2], vB[2];
#pragma unroll
    for (int a = 0; a < 2; a++) {
        int ky = pr + 2 * a; int t = oy + ky - 2;
        rofs[a] = (t >> 1) * Win;
        vy[a] = (t >= 0) && ((t >> 1) < Hin);
        tapy[a] = ky;
        int kx = q + 2 * a;
        int sA = ox0 + kx - 2;
        ixA[a] = sA >> 1; vA[a] = (sA >= 0) && ((sA >> 1) < Win);
        int sB = sA + 16;
        ixB[a] = sB >> 1; vB[a] = (sB >= 0) && ((sB >> 1) < Win);
        tapx[a] = kx;
    }

    __shared__ float wsm[32][16][16];

    ull acc[2][8];
#pragma unroll
    for (int pp = 0; pp < 2; pp++)
#pragma unroll
        for (int j = 0; j < 8; j++) acc[pp][j] = 0ull;

    for (int ic0 = 0; ic0 < Cin; ic0 += 32) {
        const int icc = min(32, Cin - ic0);
        __syncthreads();
        for (int i = tid; i < icc * 256; i += 256) {
            int c = i >> 8, rem = i & 255, t = rem >> 4, o = rem & 15;
            float wv = 0.f;
            if (oc0 + o < Cout)
                wv = w[(((oc0 + o) * Cin + ic0 + c) << 4) + t];
            wsm[c][t][o] = wv;
        }
        __syncthreads();

        const float* xp = x + ((size_t)(n * Cin + ic0) * Hin) * Win;
        for (int c = 0; c < icc; c++) {
            const float* xc = xp + (size_t)c * Hin * Win;
#pragma unroll
            for (int a = 0; a < 2; a++) {
                if (!vy[a]) continue;
                const float* xr = xc + rofs[a];
#pragma unroll
                for (int b2 = 0; b2 < 2; b2++) {
                    float v0 = vA[b2] ? __ldg(&xr[ixA[b2]]) : 0.f;
                    float v1 = vB[b2] ? __ldg(&xr[ixB[b2]]) : 0.f;
                    ull v0d = pack2(v0, v0);
                    ull v1d = pack2(v1, v1);
                    const ull* wp = (const ull*)&wsm[c][tapy[a] * 4 + tapx[b2]][0];
#pragma unroll
                    for (int j = 0; j < 8; j++) {
                        ull wj = wp[j];
                        ffma2(acc[0][j], v0d, wj);
                        ffma2(acc[1][j], v1d, wj);
                    }
                }
            }
        }
    }

#pragma unroll
    for (int pp = 0; pp < 2; pp++) {
        int ox = ox0 + 16 * pp;
        if (ox >= Wout) continue;
#pragma unroll
        for (int j = 0; j < 8; j++) {
            float2 r = unpack2(acc[pp][j]);
            int oc = oc0 + 2 * j;
            if (oc < Cout) {
                float v = r.x + bias[oc];
                if (relu) v = fmaxf(v, 0.f);
                y[(((size_t)n * Cout + oc) * Hout + oy) * Wout + ox] = v;
            }
            if (oc + 1 < Cout) {
                float v = r.y + bias[oc + 1];
                if (relu) v = fmaxf(v, 0.f);
                y[(((size_t)n * Cout + oc + 1) * Hout + oy) * Wout + ox] = v;
            }
        }
    }
}

// ---------------------------------------------------------------------------
// R4 8-oc deconv (verified) — used for deconv3 (Cout=3).
// ---------------------------------------------------------------------------
__global__ __launch_bounds__(256)
void deconv_k4s2(const float* __restrict__ x, const float* __restrict__ w,
                 const float* __restrict__ bias, float* __restrict__ y,
                 int N, int Cin, int Cout, int Hin, int Win, int relu)
{
    const int Hout = Hin << 1, Wout = Win << 1;
    const int ng = (Cout + 7) >> 3;
    const int n  = blockIdx.z / ng;
    const int oc0 = (blockIdx.z % ng) << 3;
    const int ox0 = blockIdx.x * 32 + threadIdx.x;
    const int oy  = blockIdx.y * 16 + threadIdx.y;
    const int tid = threadIdx.y * 16 + threadIdx.x;

    const int p = oy & 1, q = ox0 & 1;
    int iyv[2], tapy[2]; bool vy[2];
    int ixA[2], ixB[2], tapx[2]; bool vA[2], vB[2];
#pragma unroll
    for (int a = 0; a < 2; a++) {
        int ky = p + 2 * a; int t = oy + ky - 2;
        iyv[a] = t >> 1; vy[a] = (t >= 0) && ((t >> 1) < Hin); tapy[a] = ky;
        int kx = q + 2 * a;
        int sA = ox0 + kx - 2;
        ixA[a] = sA >> 1; vA[a] = (sA >= 0) && ((sA >> 1) < Win);
        int sB = sA + 16;
        ixB[a] = sB >> 1; vB[a] = (sB >= 0) && ((sB >> 1) < Win);
        tapx[a] = kx;
    }

    __shared__ float wsm[64][16][8];

    ull acc[2][4];
#pragma unroll
    for (int pp = 0; pp < 2; pp++)
#pragma unroll
        for (int j = 0; j < 4; j++) acc[pp][j] = 0ull;

    for (int ic0 = 0; ic0 < Cin; ic0 += 64) {
        const int icc = min(64, Cin - ic0);
        __syncthreads();
        for (int i = tid; i < icc * 128; i += 256) {
            int c = i >> 7, rem = i & 127, t = rem >> 3, o = rem & 7;
            float wv = 0.f;
            if (oc0 + o < Cout)
                wv = w[(((oc0 + o) * Cin + ic0 + c) << 4) + t];
            wsm[c][t][o] = wv;
        }
        __syncthreads();

        const float* xp = x + ((size_t)(n * Cin + ic0) * Hin) * Win;
        for (int c = 0; c < icc; c++) {
            const float* xc = xp + (size_t)c * Hin * Win;
#pragma unroll
            for (int a = 0; a < 2; a++) {
                if (!vy[a]) continue;
                const float* xr = xc + iyv[a] * Win;
#pragma unroll
                for (int b2 = 0; b2 < 2; b2++) {
                    float v0 = vA[b2] ? __ldg(&xr[ixA[b2]]) : 0.f;
                    float v1 = vB[b2] ? __ldg(&xr[ixB[b2]]) : 0.f;
                    ull v0d = pack2(v0, v0);
                    ull v1d = pack2(v1, v1);
                    const ull* wp = (const ull*)&wsm[c][tapy[a] * 4 + tapx[b2]][0];
#pragma unroll
                    for (int j = 0; j < 4; j++) {
                        ull wj = wp[j];
                        ffma2(acc[0][j], v0d, wj);
                        ffma2(acc[1][j], v1d, wj);
                    }
                }
            }
        }
    }

#pragma unroll
    for (int pp = 0; pp < 2; pp++) {
        int ox = ox0 + 16 * pp;
        if (ox >= Wout) continue;
#pragma unroll
        for (int j = 0; j < 4; j++) {
            float2 r = unpack2(acc[pp][j]);
            int oc = oc0 + 2 * j;
            if (oc < Cout) {
                float v = r.x + bias[oc];
                if (relu) v = fmaxf(v, 0.f);
                y[(((size_t)n * Cout + oc) * Hout + oy) * Wout + ox] = v;
            }
            if (oc + 1 < Cout) {
                float v = r.y + bias[oc + 1];
                if (relu) v = fmaxf(v, 0.f);
                y[(((size_t)n * Cout + oc + 1) * Hout + oy) * Wout + ox] = v;
            }
        }
    }
}

// ---------------------------------------------------------------------------
// feat [B,256,32,32] -> tok [B*1024, 256]
// ---------------------------------------------------------------------------
__global__ __launch_bounds__(1024)
void transpose_feat(const float* __restrict__ feat, float* __restrict__ tok)
{
    __shared__ float sm[32][33];
    const int hw0 = blockIdx.x * 32, c0 = blockIdx.y * 32, b = blockIdx.z;
    const int tx = threadIdx.x, ty = threadIdx.y;
    sm[ty][tx] = feat[((size_t)(b * 256 + c0 + ty)) * 1024 + hw0 + tx];
    __syncthreads();
    tok[((size_t)(b * 1024 + hw0 + ty)) * 256 + c0 + tx] = sm[tx][ty];
}

// ---------------------------------------------------------------------------
// Argmax GEMM v3: As persistent in smem; Bs WARP-PRIVATE (each warp only ever
// reads rows f+16*nn with f = 2w,2w+1) -> no per-stage block barriers, only
// __syncwarp.  Double-buffered per-warp Bs + register prefetch.
// smem: As 64x258 (66KB) + Bsw 8x2x8x66 (33.8KB) + rv/ri (8KB) = 108KB.
// ---------------------------------------------------------------------------
#define AS_STRIDE 258
#define BSW_STRIDE 66
#define GEMM_SMEM_BYTES ((64*AS_STRIDE + 8*2*8*BSW_STRIDE + 64*16 + 64*16) * 4)

__global__ __launch_bounds__(256, 2)
void argmax_gemm(const float* __restrict__ tok, const float* __restrict__ cb,
                 float* __restrict__ pv, int* __restrict__ pi)
{
    extern __shared__ float dyn[];
    float (*As)[AS_STRIDE] = (float (*)[AS_STRIDE])dyn;
    // Bsw[warp][buf][localrow][col]
    float (*Bsw)[2][8][BSW_STRIDE] = (float (*)[2][8][BSW_STRIDE])(dyn + 64 * AS_STRIDE);
    float (*rv)[16] = (float (*)[16])(dyn + 64 * AS_STRIDE + 8 * 2 * 8 * BSW_STRIDE);
    int   (*ri)[16] = (int   (*)[16])(dyn + 64 * AS_STRIDE + 8 * 2 * 8 * BSW_STRIDE + 64 * 16);

    const int tid  = threadIdx.x;
    const int wid  = tid >> 5;            // warp 0..7
    const int lane = tid & 31;
    const int e    = tid & 15;            // token sub-row 0..15
    const int fsel = (lane >> 4);         // 0/1
    const int f    = 2 * wid + fsel;      // cb sub-row 0..15
    const int t0 = (blockIdx.x >> 1) * 64;
    const int half = blockIdx.x & 1;
    const int jhalf0 = half * 4096;

    // As fill mapping (block-wide)
    const int fr  = tid >> 2;
    const int fca = (tid & 3) << 6;

    // Bs fill mapping (warp-local): lane -> localrow lr 0..7, colseg 0/16/32/48
    const int lr   = lane >> 2;
    const int fcsb = (lane & 3) << 4;
    // local row lr -> global cb row offset within 64-row chunk
    const int growofs = 2 * wid + (lr & 1) + 16 * (lr >> 1);

    // ---- fill As once ----
    {
        const float4* src = (const float4*)&tok[(size_t)(t0 + fr) * 256 + fca];
#pragma unroll
        for (int u = 0; u < 16; u++) {
            float4 v = src[u];
            float* d = &As[fr][fca + 4 * u];
            *(float2*)&d[0] = make_float2(v.x, v.y);
            *(float2*)&d[2] = make_float2(v.z, v.w);
        }
    }

    // ---- warp-private prefetch of stage 0 ----
    float4 pre[4];
    {
        const float4* src = (const float4*)&cb[(size_t)(jhalf0 + growofs) * 256 + fcsb];
#pragma unroll
        for (int u = 0; u < 4; u++) pre[u] = src[u];
        float* d = &Bsw[wid][0][lr][fcsb];
#pragma unroll
        for (int u = 0; u < 4; u++) {
            *(float2*)&d[4 * u]     = make_float2(pre[u].x, pre[u].y);
            *(float2*)&d[4 * u + 2] = make_float2(pre[u].z, pre[u].w);
        }
    }
    __syncthreads();   // As visible to all warps; Bs stage 0 visible in-warp

    float bv[4]; int bi[4];
#pragma unroll
    for (int m = 0; m < 4; m++) { bv[m] = -INFINITY; bi[m] = 0; }

    ull cacc[4][4];

    for (int s = 0; s < 256; s++) {
        const int buf = s & 1;
        const int k0 = (s & 3) << 6;

        if ((s & 3) == 0) {
#pragma unroll
            for (int m = 0; m < 4; m++)
#pragma unroll
                for (int nn = 0; nn < 4; nn++) cacc[m][nn] = 0ull;
        }

        if (s < 255) {   // register prefetch of next stage (warp-local)
            const int s1 = s + 1;
            const int jb = jhalf0 + (s1 >> 2) * 64;
            const int k1 = (s1 & 3) << 6;
            const float4* src = (const float4*)&cb[(size_t)(jb + growofs) * 256 + k1 + fcsb];
#pragma unroll
            for (int u = 0; u < 4; u++) pre[u] = src[u];
        }

#pragma unroll 8
        for (int kk = 0; kk < 32; kk++) {
            const int ka = k0 + 2 * kk;
            const int kb = 2 * kk;
            ull a2[4], b2[4];
#pragma unroll
            for (int m = 0; m < 4; m++)
                a2[m] = *(const ull*)&As[e + 16 * m][ka];
#pragma unroll
            for (int nn = 0; nn < 4; nn++)
                b2[nn] = *(const ull*)&Bsw[wid][buf][2 * nn + fsel][kb];
#pragma unroll
            for (int m = 0; m < 4; m++)
#pragma unroll
                for (int nn = 0; nn < 4; nn++)
                    ffma2(cacc[m][nn], a2[m], b2[nn]);
        }

        if ((s & 3) == 3) {
            const int jbase = jhalf0 + (s >> 2) * 64;
#pragma unroll
            for (int m = 0; m < 4; m++)
#pragma unroll
                for (int nn = 0; nn < 4; nn++) {
                    float2 sv = unpack2(cacc[m][nn]);
                    float v = sv.x + sv.y;
                    int j = jbase + f + 16 * nn;
                    if (v > bv[m] || (v == bv[m] && j < bi[m])) { bv[m] = v; bi[m] = j; }
                }
        }

        if (s < 255) {
            __syncwarp();   // all lanes done reading buf (s+1)&1 from stage s-1
            float* d = &Bsw[wid][(s + 1) & 1][lr][fcsb];
#pragma unroll
            for (int u = 0; u < 4; u++) {
                *(float2*)&d[4 * u]     = make_float2(pre[u].x, pre[u].y);
                *(float2*)&d[4 * u + 2] = make_float2(pre[u].z, pre[u].w);
            }
            __syncwarp();   // stores visible before next stage reads
        }
    }

#pragma unroll
    for (int m = 0; m < 4; m++) { rv[e + 16 * m][f] = bv[m]; ri[e + 16 * m][f] = bi[m]; }
    __syncthreads();
    if (tid < 64) {
        float best = rv[tid][0]; int bidx = ri[tid][0];
#pragma unroll
        for (int g = 1; g < 16; g++) {
            float v = rv[tid][g]; int j = ri[tid][g];
            if (v > best || (v == best && j < bidx)) { best = v; bidx = j; }
        }
        pv[half * (B * 1024) + t0 + tid] = best;
        pi[half * (B * 1024) + t0 + tid] = bidx;
    }
}

__global__ void merge_idx(const float* __restrict__ pv, const int* __restrict__ pi,
                          int* __restrict__ idx)
{
    int t = blockIdx.x * 256 + threadIdx.x;
    if (t >= B * 1024) return;
    float v0 = pv[t], v1 = pv[B * 1024 + t];
    idx[t] = (v1 > v0) ? pi[B * 1024 + t] : pi[t];   // half 0 wins ties (lower j)
}

__global__ __launch_bounds__(1024)
void gather_q(const float* __restrict__ cb, const int* __restrict__ idx,
              float* __restrict__ q)
{
    __shared__ float sm[32][33];
    __shared__ int rows[32];
    const int hw0 = blockIdx.x * 32, c0 = blockIdx.y * 32, b = blockIdx.z;
    const int tx = threadIdx.x, ty = threadIdx.y;
    if (ty == 0) rows[tx] = idx[b * 1024 + hw0 + tx];
    __syncthreads();
    sm[ty][tx] = cb[(size_t)rows[ty] * 256 + c0 + tx];
    __syncthreads();
    q[((size_t)(b * 256 + c0 + ty)) * 1024 + hw0 + tx] = sm[tx][ty];
}

__global__ void idx_to_float(const int* __restrict__ idx, float* __restrict__ out)
{
    int t = blockIdx.x * 256 + threadIdx.x;
    if (t < B * 1024) out[t] = (float)idx[t];
}

// ---------------------------------------------------------------------------
// Launch
// ---------------------------------------------------------------------------
extern "C" void kernel_launch(void* const* d_in, const int* in_sizes, int n_in,
                              void* d_out, int out_size)
{
    const float* x   = (const float*)d_in[0];
    const float* ew1 = (const float*)d_in[1];
    const float* eb1 = (const float*)d_in[2];
    const float* ew2 = (const float*)d_in[3];
    const float* eb2 = (const float*)d_in[4];
    const float* ew3 = (const float*)d_in[5];
    const float* eb3 = (const float*)d_in[6];
    const float* cb  = (const float*)d_in[7];
    const float* dw1 = (const float*)d_in[8];
    const float* db1 = (const float*)d_in[9];
    const float* dw2 = (const float*)d_in[10];
    const float* db2 = (const float*)d_in[11];
    const float* dw3 = (const float*)d_in[12];
    const float* db3 = (const float*)d_in[13];
    float* out = (float*)d_out;

    float *h1, *h2, *feat, *tok, *q, *d1, *d2, *pv;
    int *idxp, *pip;
    cudaGetSymbolAddress((void**)&h1,  g_h1);
    cudaGetSymbolAddress((void**)&h2,  g_h2);
    cudaGetSymbolAddress((void**)&feat,g_feat);
    cudaGetSymbolAddress((void**)&tok, g_tok);
    cudaGetSymbolAddress((void**)&q,   g_q);
    cudaGetSymbolAddress((void**)&d1,  g_d1);
    cudaGetSymbolAddress((void**)&d2,  g_d2);
    cudaGetSymbolAddress((void**)&idxp,g_idx);
    cudaGetSymbolAddress((void**)&pv,  g_pv);
    cudaGetSymbolAddress((void**)&pip, g_pi);

    static int smem_set = 0;
    if (!smem_set) {
        cudaFuncSetAttribute(argmax_gemm,
                             cudaFuncAttributeMaxDynamicSharedMemorySize,
                             GEMM_SMEM_BYTES);
        smem_set = 1;
    }

    dim3 b16(16, 16);

    // encoder: 16-oc blocks, 32x16 tiles
    conv_k4s2_oc16<<<dim3(4, 8, B * 4),  b16>>>(x,  ew1, eb1, h1,   B,   3,  64, 256, 256, 1);
    conv_k4s2_oc16<<<dim3(2, 4, B * 8),  b16>>>(h1, ew2, eb2, h2,   B,  64, 128, 128, 128, 1);
    conv_k4s2_oc16<<<dim3(1, 2, B * 16), b16>>>(h2, ew3, eb3, feat, B, 128, 256,  64,  64, 0);

    // quantize
    transpose_feat<<<dim3(32, 8, B), dim3(32, 32)>>>(feat, tok);
    argmax_gemm<<<(B * 1024 / 64) * 2, 256, GEMM_SMEM_BYTES>>>(tok, cb, pv, pip);
    merge_idx<<<(B * 1024 + 255) / 256, 256>>>(pv, pip, idxp);
    gather_q<<<dim3(32, 8, B), dim3(32, 32)>>>(cb, idxp, q);

    // decoder: deconv1/deconv2 16-oc; deconv3 (Cout=3) 8-oc
    deconv_k4s2_oc16<<<dim3(2, 4, B * 8), b16>>>(q,  dw1, db1, d1, B, 256, 128, 32, 32, 1);
    deconv_k4s2_oc16<<<dim3(4, 8, B * 4), b16>>>(d1, dw2, db2, d2, B, 128,  64, 64, 64, 1);
    deconv_k4s2    <<<dim3(8, 16, B),     b16>>>(d2, dw3, db3, out, B, 64,   3, 128, 128, 0);

    const int recon_elems = B * 3 * 256 * 256;
    if (out_size >= recon_elems + B * 1024)
        idx_to_float<<<(B * 1024 + 255) / 256, 256>>>(idxp, out + recon_elems);
}